// round 2
// baseline (speedup 1.0000x reference)
#include <cuda_runtime.h>
#include <cuda_bf16.h>

// Problem: y[n,k] = log( sum_l clip(mu[n,l],EPS) * softmax(leaf_scores[l,:])[k] )
// N=32768, L=256, C=64. Pure-positive mixture -> no logsumexp shift needed in fp32.

#define LL 256
#define CC 64
#define EPSV 1e-12f
#define TPB 128

__device__ float g_Q[LL * CC];  // softmax(leaf_scores) -- device-global scratch (no allocs)

// ---------------- Kernel 1: per-leaf softmax (tiny) ----------------
// grid = L blocks, 32 threads; each thread owns k = lane and k = lane+32.
__global__ void softmax_kernel(const float* __restrict__ s) {
    const int l = blockIdx.x;
    const int t = threadIdx.x;
    const float a = s[l * CC + t];
    const float b = s[l * CC + t + 32];
    float m = fmaxf(a, b);
    #pragma unroll
    for (int off = 16; off > 0; off >>= 1)
        m = fmaxf(m, __shfl_xor_sync(0xFFFFFFFFu, m, off));
    const float ea = expf(a - m);
    const float eb = expf(b - m);
    float sum = ea + eb;
    #pragma unroll
    for (int off = 16; off > 0; off >>= 1)
        sum += __shfl_xor_sync(0xFFFFFFFFu, sum, off);
    const float inv = 1.0f / sum;
    g_Q[l * CC + t]      = ea * inv;
    g_Q[l * CC + t + 32] = eb * inv;
}

// ---------------- Kernel 2: main GEMM + log ----------------
// One row n per thread. Q staged in smem (64KB). 32 packed f32x2 accumulators.
// Inner loop per leaf l: broadcast LDS.128 of Q row + fma.rn.f32x2.

#define FMA_F32X2(d, a, b, c) \
    asm("fma.rn.f32x2 %0, %1, %2, %3;" : "=l"(d) : "l"(a), "l"(b), "l"(c))

__global__ void __launch_bounds__(TPB) leafmix_kernel(
    const float* __restrict__ mu, float* __restrict__ out, int N)
{
    __shared__ float Qs[LL * CC];  // 64 KB

    // cooperative load of Q into smem (coalesced float4), 32 iters per thread
    {
        const float4* gq = (const float4*)g_Q;
        float4* sq = (float4*)Qs;
        for (int i = threadIdx.x; i < (LL * CC) / 4; i += TPB)
            sq[i] = gq[i];
    }
    __syncthreads();

    const int n = blockIdx.x * TPB + threadIdx.x;
    if (n >= N) return;

    const float4* mu4 = (const float4*)(mu + (size_t)n * LL);

    unsigned long long acc[CC / 2];
    #pragma unroll
    for (int i = 0; i < CC / 2; i++) acc[i] = 0ULL;  // (0.0f, 0.0f)

    for (int l0 = 0; l0 < LL; l0 += 4) {
        const float4 m4 = mu4[l0 >> 2];
        const float mv[4] = {m4.x, m4.y, m4.z, m4.w};
        #pragma unroll
        for (int j = 0; j < 4; j++) {
            const float mc = fmaxf(mv[j], EPSV);
            const unsigned int mb = __float_as_uint(mc);
            unsigned long long mm;
            asm("mov.b64 %0, {%1, %2};" : "=l"(mm) : "r"(mb), "r"(mb));
            const ulonglong2* q2 = (const ulonglong2*)&Qs[(l0 + j) * CC];
            #pragma unroll
            for (int kp = 0; kp < CC / 4; kp++) {  // 16 x LDS.128 (broadcast, conflict-free)
                const ulonglong2 q = q2[kp];
                FMA_F32X2(acc[2 * kp],     mm, q.x, acc[2 * kp]);
                FMA_F32X2(acc[2 * kp + 1], mm, q.y, acc[2 * kp + 1]);
            }
        }
    }

    // epilogue: unpack, log, store
    float* op = out + (size_t)n * CC;
    #pragma unroll
    for (int kp = 0; kp < CC / 2; kp++) {
        unsigned int lo, hi;
        asm("mov.b64 {%0, %1}, %2;" : "=r"(lo), "=r"(hi) : "l"(acc[kp]));
        float2 r;
        r.x = logf(__uint_as_float(lo));
        r.y = logf(__uint_as_float(hi));
        ((float2*)op)[kp] = r;
    }
}

extern "C" void kernel_launch(void* const* d_in, const int* in_sizes, int n_in,
                              void* d_out, int out_size) {
    const float* mu = (const float*)d_in[0];           // (N, L) fp32
    const float* leaf_scores = (const float*)d_in[1];  // (L, C) fp32
    float* out = (float*)d_out;                        // (N, C) fp32

    const int N = in_sizes[0] / LL;

    softmax_kernel<<<LL, 32>>>(leaf_scores);
    const int grid = (N + TPB - 1) / TPB;
    leafmix_kernel<<<grid, TPB>>>(mu, out, N);
}

// round 3
// speedup vs baseline: 1.0628x; 1.0628x over previous
#include <cuda_runtime.h>
#include <cuda_bf16.h>

// y[n,k] = log( sum_l clip(mu[n,l],EPS) * softmax(leaf_scores[l,:])[k] )
// N=32768, L=256, C=64. Positive mixture -> plain fp32 dot + log, no lse shift.

#define LL 256
#define CC 64
#define EPSV 1e-12f

#define BN 128          // output rows per block
#define TPB 256         // threads per block
#define CH 32           // leaves per mu chunk
#define NCH (LL / CH)   // 8 chunks
#define MU_STRIDE 130   // floats per transposed-mu row (128 + 2 pad, 8B-aligned rows)

__device__ float g_Q[LL * CC];  // softmax(leaf_scores), device-global scratch

// ---------------- Kernel 1: per-leaf softmax ----------------
__global__ void softmax_kernel(const float* __restrict__ s) {
    const int l = blockIdx.x;
    const int t = threadIdx.x;
    const float a = s[l * CC + t];
    const float b = s[l * CC + t + 32];
    float m = fmaxf(a, b);
    #pragma unroll
    for (int off = 16; off > 0; off >>= 1)
        m = fmaxf(m, __shfl_xor_sync(0xFFFFFFFFu, m, off));
    const float ea = expf(a - m);
    const float eb = expf(b - m);
    float sum = ea + eb;
    #pragma unroll
    for (int off = 16; off > 0; off >>= 1)
        sum += __shfl_xor_sync(0xFFFFFFFFu, sum, off);
    const float inv = 1.0f / sum;
    g_Q[l * CC + t]      = ea * inv;
    g_Q[l * CC + t + 32] = eb * inv;
}

// ---------------- Kernel 2: register-tiled mixture GEMM + log ----------------
// Block tile: 128 n x 64 k. Thread tile: 8n x 4k (rows packed in pairs for f32x2).
// Q (64KB) staged whole in smem; mu streamed in 32-leaf transposed chunks,
// double-buffered with register prefetch.

#define FMA_F32X2(d, a, b, c) \
    asm("fma.rn.f32x2 %0, %1, %2, %3;" : "=l"(d) : "l"(a), "l"(b), "l"(c))
#define PACK2(d, x) \
    asm("mov.b64 %0, {%1, %1};" : "=l"(d) : "r"(__float_as_uint(x)))

extern __shared__ float s_mem[];  // [ Qs: LL*CC | mu_t: 2 * CH*MU_STRIDE ]

__global__ void __launch_bounds__(TPB, 2) leafmix_kernel(
    const float* __restrict__ mu, float* __restrict__ out, int N)
{
    float* Qs = s_mem;                       // [LL][CC]
    float* mu_t = s_mem + LL * CC;           // [2][CH][MU_STRIDE]

    const int tid = threadIdx.x;
    const int tc = tid & 15;                 // k-group: cols tc*4 .. tc*4+3
    const int tr = tid >> 4;                 // n-group: rows tr*8 .. tr*8+7
    const int n0 = blockIdx.x * BN;

    const float* mu_base = mu + (size_t)n0 * LL;

    float ldreg[16];

    // ---- prefetch chunk 0 into registers (row = coalesced 128B per warp) ----
    #pragma unroll
    for (int j = 0; j < 16; j++) {
        const int i = tid + j * TPB;
        const int row = i >> 5, l = i & 31;
        ldreg[j] = fmaxf(__ldg(&mu_base[(size_t)row * LL + l]), EPSV);
    }

    // ---- stage Q into smem (coalesced float4) ----
    {
        const float4* gq = (const float4*)g_Q;
        float4* sq = (float4*)Qs;
        #pragma unroll
        for (int j = 0; j < (LL * CC / 4) / TPB; j++)
            sq[tid + j * TPB] = gq[tid + j * TPB];
    }

    // ---- store chunk 0 transposed: mu_t[l][row] ----
    #pragma unroll
    for (int j = 0; j < 16; j++) {
        const int i = tid + j * TPB;
        const int row = i >> 5, l = i & 31;
        mu_t[l * MU_STRIDE + row] = ldreg[j];
    }
    __syncthreads();

    unsigned long long acc[16];  // acc[r2*4+k]: lo=row 2*r2, hi=row 2*r2+1, col k
    #pragma unroll
    for (int i = 0; i < 16; i++) acc[i] = 0ULL;

    #pragma unroll 1
    for (int c = 0; c < NCH; c++) {
        // prefetch next chunk to registers (overlaps with compute below)
        if (c + 1 < NCH) {
            const float* src = mu_base + (c + 1) * CH;
            #pragma unroll
            for (int j = 0; j < 16; j++) {
                const int i = tid + j * TPB;
                const int row = i >> 5, l = i & 31;
                ldreg[j] = fmaxf(__ldg(&src[(size_t)row * LL + l]), EPSV);
            }
        }

        const float* mbuf = mu_t + (c & 1) * (CH * MU_STRIDE);
        const int l0 = c * CH;

        #pragma unroll 8
        for (int l = 0; l < CH; l++) {
            // mu pairs for this thread's 8 rows: 4 x LDS.64 (broadcast across tc)
            const unsigned long long* mrow =
                (const unsigned long long*)(mbuf + l * MU_STRIDE + tr * 8);
            const unsigned long long m0 = mrow[0];
            const unsigned long long m1 = mrow[1];
            const unsigned long long m2 = mrow[2];
            const unsigned long long m3 = mrow[3];

            // q scalars for this thread's 4 cols, duplicated into f32x2 lanes
            const float* qrow = &Qs[(l0 + l) * CC + tc * 4];
            unsigned long long q0, q1, q2, q3;
            PACK2(q0, qrow[0]); PACK2(q1, qrow[1]);
            PACK2(q2, qrow[2]); PACK2(q3, qrow[3]);

            FMA_F32X2(acc[0],  m0, q0, acc[0]);
            FMA_F32X2(acc[1],  m0, q1, acc[1]);
            FMA_F32X2(acc[2],  m0, q2, acc[2]);
            FMA_F32X2(acc[3],  m0, q3, acc[3]);
            FMA_F32X2(acc[4],  m1, q0, acc[4]);
            FMA_F32X2(acc[5],  m1, q1, acc[5]);
            FMA_F32X2(acc[6],  m1, q2, acc[6]);
            FMA_F32X2(acc[7],  m1, q3, acc[7]);
            FMA_F32X2(acc[8],  m2, q0, acc[8]);
            FMA_F32X2(acc[9],  m2, q1, acc[9]);
            FMA_F32X2(acc[10], m2, q2, acc[10]);
            FMA_F32X2(acc[11], m2, q3, acc[11]);
            FMA_F32X2(acc[12], m3, q0, acc[12]);
            FMA_F32X2(acc[13], m3, q1, acc[13]);
            FMA_F32X2(acc[14], m3, q2, acc[14]);
            FMA_F32X2(acc[15], m3, q3, acc[15]);
        }

        // write prefetched chunk into the other buffer (its old readers synced last iter)
        if (c + 1 < NCH) {
            float* dbuf = mu_t + ((c + 1) & 1) * (CH * MU_STRIDE);
            #pragma unroll
            for (int j = 0; j < 16; j++) {
                const int i = tid + j * TPB;
                const int row = i >> 5, l = i & 31;
                dbuf[l * MU_STRIDE + row] = ldreg[j];
            }
        }
        __syncthreads();
    }

    // ---- epilogue: unpack pairs, log, store float4 per row ----
    const int nb = n0 + tr * 8;
    #pragma unroll
    for (int r2 = 0; r2 < 4; r2++) {
        float lo[4], hi[4];
        #pragma unroll
        for (int k = 0; k < 4; k++) {
            unsigned int ulo, uhi;
            asm("mov.b64 {%0, %1}, %2;" : "=r"(ulo), "=r"(uhi) : "l"(acc[r2 * 4 + k]));
            lo[k] = logf(__uint_as_float(ulo));
            hi[k] = logf(__uint_as_float(uhi));
        }
        float4* o0 = (float4*)&out[(size_t)(nb + 2 * r2) * CC + tc * 4];
        float4* o1 = (float4*)&out[(size_t)(nb + 2 * r2 + 1) * CC + tc * 4];
        *o0 = make_float4(lo[0], lo[1], lo[2], lo[3]);
        *o1 = make_float4(hi[0], hi[1], hi[2], hi[3]);
    }
}

extern "C" void kernel_launch(void* const* d_in, const int* in_sizes, int n_in,
                              void* d_out, int out_size) {
    const float* mu = (const float*)d_in[0];           // (N, L) fp32
    const float* leaf_scores = (const float*)d_in[1];  // (L, C) fp32
    float* out = (float*)d_out;                        // (N, C) fp32

    const int N = in_sizes[0] / LL;
    const int smem_bytes = (LL * CC + 2 * CH * MU_STRIDE) * sizeof(float);

    static bool attr_set = false;
    if (!attr_set) {
        cudaFuncSetAttribute(leafmix_kernel,
                             cudaFuncAttributeMaxDynamicSharedMemorySize, smem_bytes);
        attr_set = true;
    }

    softmax_kernel<<<LL, 32>>>(leaf_scores);
    leafmix_kernel<<<N / BN, TPB, smem_bytes>>>(mu, out, N);
}

// round 5
// speedup vs baseline: 3.0321x; 2.8530x over previous
#include <cuda_runtime.h>
#include <cuda_bf16.h>
#include <cstdint>

// y[n,k] = log( sum_l clip(mu[n,l],EPS) * softmax(leaf_scores[l,:])[k] )
// N=32768, L=256, C=64.
// S = mu_hat @ Q via mma.sync m16n8k16 bf16 with hi/lo split:
//   S ~= Ah@Bh + Ah@Bl + Al@Bh  (fp32 accumulate), then log.
// ptxas target is plain sm_103 (no 'a') -> no tcgen05; HMMA is the tensor path.

#define LL 256
#define CC 64
#define EPSV 1e-12f
#define TPB 256
#define BN  128
#define ROWB 272   // bf16 per B row: 256 + 16 pad (32B) -> conflict-free LDS.64

// B matrix (Q) in mma-ready layout: [class c][leaf-permuted l'], hi then lo.
__device__ __nv_bfloat16 g_B[2][CC * ROWB];

// ---------------- Kernel 1: softmax + bf16 hi/lo split + fragment permute ----
// Leaf index permuted within 16-groups so a quad-lane LDS.64 yields the
// mma B fragment pair {k0,k1,k8,k9}: l' = 16*(l/16) + 4*((l%8)/2) + (l%2) + 2*((l%16)/8)
__global__ void softmax_kernel(const float* __restrict__ s) {
    const int l = blockIdx.x;
    const int t = threadIdx.x;
    const float a = s[l * CC + t];
    const float b = s[l * CC + t + 32];
    float m = fmaxf(a, b);
    #pragma unroll
    for (int off = 16; off > 0; off >>= 1)
        m = fmaxf(m, __shfl_xor_sync(0xFFFFFFFFu, m, off));
    const float ea = expf(a - m);
    const float eb = expf(b - m);
    float sum = ea + eb;
    #pragma unroll
    for (int off = 16; off > 0; off >>= 1)
        sum += __shfl_xor_sync(0xFFFFFFFFu, sum, off);
    const float inv = 1.0f / sum;
    const float qa = ea * inv;
    const float qb = eb * inv;

    const int i = l & 15;
    const int lp = (l & 0xF0) | ((((i & 7) >> 1) << 2) | (i & 1) | ((i >> 3) << 1));

    const __nv_bfloat16 ha = __float2bfloat16(qa);
    const __nv_bfloat16 hb = __float2bfloat16(qb);
    g_B[0][t * ROWB + lp]        = ha;
    g_B[0][(t + 32) * ROWB + lp] = hb;
    g_B[1][t * ROWB + lp]        = __float2bfloat16(qa - __bfloat162float(ha));
    g_B[1][(t + 32) * ROWB + lp] = __float2bfloat16(qb - __bfloat162float(hb));
}

// ---------------- helpers ----------------
__device__ __forceinline__ void mma_bf16(float* d,
    uint32_t a0, uint32_t a1, uint32_t a2, uint32_t a3, uint32_t b0, uint32_t b1)
{
    asm volatile("mma.sync.aligned.m16n8k16.row.col.f32.bf16.bf16.f32 "
                 "{%0,%1,%2,%3}, {%4,%5,%6,%7}, {%8,%9}, {%0,%1,%2,%3};"
                 : "+f"(d[0]), "+f"(d[1]), "+f"(d[2]), "+f"(d[3])
                 : "r"(a0), "r"(a1), "r"(a2), "r"(a3), "r"(b0), "r"(b1));
}

__device__ __forceinline__ void split2(float2 f, uint32_t& h, uint32_t& l) {
    f.x = fmaxf(f.x, EPSV);
    f.y = fmaxf(f.y, EPSV);
    __nv_bfloat162 hb = __float22bfloat162_rn(f);
    float2 hf = __bfloat1622float2(hb);
    __nv_bfloat162 lb = __float22bfloat162_rn(make_float2(f.x - hf.x, f.y - hf.y));
    h = *reinterpret_cast<uint32_t*>(&hb);
    l = *reinterpret_cast<uint32_t*>(&lb);
}

// ---------------- Kernel 2: HMMA mixture GEMM + log ----------------
extern __shared__ __nv_bfloat16 sB[];   // [2][CC*ROWB] = 69632 bytes

__global__ void __launch_bounds__(TPB, 2) leafmix_kernel(
    const float* __restrict__ mu, float* __restrict__ out)
{
    // stage B (Q hi/lo) into smem, coalesced uint4: 4352 / 256 = 17 iters exact
    {
        const uint4* gq = (const uint4*)g_B;
        uint4* sq = (uint4*)sB;
        #pragma unroll
        for (int j = 0; j < 17; j++)
            sq[threadIdx.x + j * TPB] = gq[threadIdx.x + j * TPB];
    }
    __syncthreads();

    const int tid = threadIdx.x;
    const int w = tid >> 5;
    const int lane = tid & 31;
    const int g = lane >> 2;   // row group / n index
    const int r = lane & 3;    // k quad

    const int row0 = blockIdx.x * BN + w * 16 + g;
    const float* A0 = mu + (size_t)row0 * LL;
    const float* A1 = A0 + 8 * LL;

    const __nv_bfloat16* Bh = sB;
    const __nv_bfloat16* Bl = sB + CC * ROWB;
    const int bbase = g * ROWB + r * 4;

    float acc[8][4];
    #pragma unroll
    for (int nt = 0; nt < 8; nt++)
        #pragma unroll
        for (int q = 0; q < 4; q++) acc[nt][q] = 0.0f;

    // software-pipelined A loads (each mu element loaded exactly once)
    float2 c00 = *(const float2*)(A0 + r * 2);
    float2 c01 = *(const float2*)(A0 + r * 2 + 8);
    float2 c10 = *(const float2*)(A1 + r * 2);
    float2 c11 = *(const float2*)(A1 + r * 2 + 8);

    #pragma unroll 2
    for (int kk = 0; kk < 16; kk++) {
        float2 n00, n01, n10, n11;
        if (kk < 15) {
            const int c = r * 2 + 16 * (kk + 1);
            n00 = *(const float2*)(A0 + c);
            n01 = *(const float2*)(A0 + c + 8);
            n10 = *(const float2*)(A1 + c);
            n11 = *(const float2*)(A1 + c + 8);
        }

        uint32_t ah0, al0, ah1, al1, ah2, al2, ah3, al3;
        split2(c00, ah0, al0);   // rows g,    k 0..7
        split2(c10, ah1, al1);   // rows g+8,  k 0..7
        split2(c01, ah2, al2);   // rows g,    k 8..15
        split2(c11, ah3, al3);   // rows g+8,  k 8..15

        const int ko = bbase + kk * 16;
        #pragma unroll
        for (int nt = 0; nt < 8; nt++) {
            const uint2 bh = *(const uint2*)(Bh + ko + nt * 8 * ROWB);
            const uint2 bl = *(const uint2*)(Bl + ko + nt * 8 * ROWB);
            mma_bf16(acc[nt], ah0, ah1, ah2, ah3, bh.x, bh.y);
            mma_bf16(acc[nt], ah0, ah1, ah2, ah3, bl.x, bl.y);
            mma_bf16(acc[nt], al0, al1, al2, al3, bh.x, bh.y);
        }

        c00 = n00; c01 = n01; c10 = n10; c11 = n11;
    }

    // epilogue: log + store (float2 per row per n-tile)
    float* o0 = out + (size_t)row0 * CC;
    float* o1 = o0 + 8 * CC;
    #pragma unroll
    for (int nt = 0; nt < 8; nt++) {
        *(float2*)(o0 + nt * 8 + r * 2) =
            make_float2(__logf(acc[nt][0]), __logf(acc[nt][1]));
        *(float2*)(o1 + nt * 8 + r * 2) =
            make_float2(__logf(acc[nt][2]), __logf(acc[nt][3]));
    }
}

extern "C" void kernel_launch(void* const* d_in, const int* in_sizes, int n_in,
                              void* d_out, int out_size) {
    const float* mu = (const float*)d_in[0];           // (N, L) fp32
    const float* leaf_scores = (const float*)d_in[1];  // (L, C) fp32
    float* out = (float*)d_out;                        // (N, C) fp32

    const int N = in_sizes[0] / LL;
    const int smem_bytes = 2 * CC * ROWB * (int)sizeof(__nv_bfloat16);  // 69632

    static bool attr_set = false;
    if (!attr_set) {
        cudaFuncSetAttribute(leafmix_kernel,
                             cudaFuncAttributeMaxDynamicSharedMemorySize, smem_bytes);
        attr_set = true;
    }

    softmax_kernel<<<LL, 32>>>(leaf_scores);
    leafmix_kernel<<<N / BN, TPB, smem_bytes>>>(mu, out);
}